// round 9
// baseline (speedup 1.0000x reference)
#include <cuda_runtime.h>

#define T_SEQ   128
#define NB_     13
#define T_IN_   64
#define BQ      8
#define NBLOCKS 128
#define NTHREADS 512

// ---- shared memory layout (float indices) ----
// Resident weight slab: 72 rows (18 per kg): slabrow = kg*18 + i <-> k = kg*32 + i (i<18)
#define SW_OFF   0        // [72][512] quad-interleaved: sW[row*512 + d*4 + g]
#define SP_OFF   36864    // partials: u64 P[p][kg][g][d] = 4*4*4*128 u64 = 16384 floats
#define SH_OFF   53248    // [128][8] h, k-major (1024 floats)
#define SHT_OFF  54272    // [8][132] h transposed (readout)
#define SWO_OFF  55328    // [13][132] W_out padded
#define SX_OFF   57044    // [13][12] x_t (48B row stride)
#define SMEM_FLOATS 57200
#define SMEM_BYTES  (SMEM_FLOATS * 4)   // 228800 <= 232448

// quad-interleaved: g_W4[k*512 + d*4 + g] = W_hh[(d+128g)*128 + k]
__device__ float g_W4[128 * 512];
__device__ float g_Wih4[NB_ * 512];   // g_Wih4[n*512 + d*4 + g] = W_ih[(d+128g)*13 + n]
__device__ float g_bias4[512];        // g_bias4[d*4+g] = (b_ih+b_hh)[d+128g]

typedef unsigned long long ull;

// ---------- helpers ----------
__device__ __forceinline__ unsigned sptr(const void* p) {
    return (unsigned)__cvta_generic_to_shared(p);
}
__device__ __forceinline__ ull pk2(float v) {
    ull r; unsigned u = __float_as_uint(v);
    asm("mov.b64 %0, {%1, %1};" : "=l"(r) : "r"(u));
    return r;
}
__device__ __forceinline__ ull pack2(float lo, float hi) {
    ull r;
    asm("mov.b64 %0, {%1, %2};" : "=l"(r) : "r"(__float_as_uint(lo)), "r"(__float_as_uint(hi)));
    return r;
}
__device__ __forceinline__ void fma2(ull& a, ull b, ull c) {
    asm("fma.rn.f32x2 %0, %1, %2, %0;" : "+l"(a) : "l"(b), "l"(c));
}
__device__ __forceinline__ void add2(ull& a, ull b) {
    asm("add.rn.f32x2 %0, %0, %1;" : "+l"(a) : "l"(b));
}
__device__ __forceinline__ void lds_v2u64(ull& a, ull& b, unsigned addr) {
    asm volatile("ld.shared.v2.u64 {%0, %1}, [%2];" : "=l"(a), "=l"(b) : "r"(addr));
}
__device__ __forceinline__ ull lds_u64(unsigned addr) {
    ull v;
    asm volatile("ld.shared.b64 %0, [%1];" : "=l"(v) : "r"(addr));
    return v;
}
__device__ __forceinline__ void sts_u64(unsigned addr, ull v) {
    asm volatile("st.shared.b64 [%0], %1;" :: "r"(addr), "l"(v) : "memory");
}
__device__ __forceinline__ float lo2(ull a) { return __uint_as_float((unsigned)(a & 0xffffffffull)); }
__device__ __forceinline__ float hi2(ull a) { return __uint_as_float((unsigned)(a >> 32)); }
__device__ __forceinline__ float sigm(float v) { return __fdividef(1.0f, 1.0f + __expf(-v)); }
__device__ __forceinline__ float tanh_(float v) { return __fdividef(2.0f, 1.0f + __expf(-2.0f * v)) - 1.0f; }

// one k, all 4 gates of dim d, 8 batch: 2 LDS.128(bcast) + 16 fma2
__device__ __forceinline__ void do_k4(unsigned haddr, float4 wq, ull (&A)[4][4])
{
    ull h01, h23, h45, h67;
    lds_v2u64(h01, h23, haddr);
    lds_v2u64(h45, h67, haddr + 16);
    ull wi = pk2(wq.x), wf = pk2(wq.y), wg = pk2(wq.z), wo = pk2(wq.w);
    fma2(A[0][0], h01, wi); fma2(A[0][1], h23, wi); fma2(A[0][2], h45, wi); fma2(A[0][3], h67, wi);
    fma2(A[1][0], h01, wf); fma2(A[1][1], h23, wf); fma2(A[1][2], h45, wf); fma2(A[1][3], h67, wf);
    fma2(A[2][0], h01, wg); fma2(A[2][1], h23, wg); fma2(A[2][2], h45, wg); fma2(A[2][3], h67, wg);
    fma2(A[3][0], h01, wo); fma2(A[3][1], h23, wo); fma2(A[3][2], h45, wo); fma2(A[3][3], h67, wo);
}

// ---------- prep ----------
__global__ void prep_kernel(const float* __restrict__ W_hh,
                            const float* __restrict__ W_ih,
                            const float* __restrict__ b_ih,
                            const float* __restrict__ b_hh)
{
    int idx = blockIdx.x * blockDim.x + threadIdx.x;
    if (idx < 128 * 512) {
        int k = idx >> 9, r = idx & 511;
        int d = r >> 2, g = r & 3;
        g_W4[idx] = W_hh[(d + 128 * g) * 128 + k];
    }
    if (idx < NB_ * 512) {
        int n = idx >> 9, r = idx & 511;
        int d = r >> 2, g = r & 3;
        g_Wih4[idx] = W_ih[(d + 128 * g) * NB_ + n];
    }
    if (idx < 512) {
        int d = idx >> 2, g = idx & 3;
        g_bias4[idx] = b_ih[d + 128 * g] + b_hh[d + 128 * g];
    }
}

// ---------- main persistent LSTM kernel ----------
__global__ void __launch_bounds__(NTHREADS, 1)
lstm_main(const float* __restrict__ x, const float* __restrict__ W_out,
          const float* __restrict__ b_out, float* __restrict__ out)
{
    extern __shared__ float sm[];
    float* sW  = sm + SW_OFF;
    float* sH  = sm + SH_OFF;
    float* sHT = sm + SHT_OFF;
    float* sWo = sm + SWO_OFF;
    float* sX  = sm + SX_OFF;

    const int t  = threadIdx.x;
    const int d  = t & 127;
    const int kg = t >> 7;          // 0..3 ; also my batch-pair q and warp-group
    const int b0 = blockIdx.x * BQ;

    // ---- cooperative smem fill ----
    {
        const float4* src = (const float4*)g_W4;
        float4* dst = (float4*)sW;
        for (int i = t; i < 72 * 128; i += NTHREADS) {
            int r = i >> 7, c = i & 127;
            int rkg = r / 18, ri = r - rkg * 18;
            dst[i] = src[(rkg * 32 + ri) * 128 + c];
        }
        for (int i = t; i < NB_ * 128; i += NTHREADS) {
            int n = i >> 7, dd = i & 127;
            sWo[n * 132 + dd] = W_out[i];
        }
        for (int i = t; i < 128 * 8; i += NTHREADS) sH[i] = 0.0f;
    }

    const unsigned hb  = sptr(sH);
    const unsigned xbb = sptr(sX);
    const unsigned Pb  = sptr(sm + SP_OFF);

    // per-kg pointers
    const float* swb = sW + (kg * 18) * 512 + d * 4;                       // 18 resident rows
    const float4* gp4 = ((const float4*)g_W4) + (kg * 32 + 18) * 128 + d;  // 14 streamed rows
    const unsigned myH = hb + (unsigned)(kg * 32 * 32);                    // h base (k = 32*kg)

    // x-part: kg handles n in [4kg, 4kg+ncnt)
    const int nbase = kg * 4;
    const int ncnt  = (kg == 3) ? 1 : 4;
    float4 wxq[4];
    #pragma unroll
    for (int m = 0; m < 4; m++)
        if (m < ncnt) wxq[m] = __ldg(((const float4*)g_Wih4) + (nbase + m) * 128 + d);

    const float4 bv = __ldg(((const float4*)g_bias4) + d);

    // c-state: batch pair q = kg (batches 2kg, 2kg+1) of dim d
    float cc0 = 0.0f, cc1 = 0.0f;

    // readout mapping: threads 384..487 (kg3, lightest x-part)
    const int yi = t - 384;
    const bool yth = (yi >= 0) && (yi < BQ * NB_);
    const int yb = yth ? (yi / NB_) : 0;
    const int yn = yth ? (yi - yb * NB_) : 0;
    const float bo = yth ? __ldg(b_out + yn) : 0.0f;
    const int rowx = yth ? ((b0 + yb) * (T_SEQ * NB_) + yn) : 0;

    float xreg = 0.0f;
    if (yth) {
        float x0 = x[rowx];
        sX[yn * 12 + yb] = x0;
        out[rowx] = x0;                  // out[:,0] = x[:,0]
        xreg = x[rowx + NB_];            // prefetch x[:,1]
    }
    __syncthreads();

    for (int s = 0; s < T_SEQ - 1; s++) {
        // ---- hidden readout of y_s (concurrent with h-GEMM below) ----
        if (s > 0 && yth) {
            const float4* h4 = (const float4*)(sHT + yb * 132);
            const float4* w4 = (const float4*)(sWo + yn * 132);
            float ac0 = bo, ac1 = 0.0f, ac2 = 0.0f, ac3 = 0.0f;
            #pragma unroll 8
            for (int qq = 0; qq < 32; qq++) {
                float4 hq = h4[qq];
                float4 wq = w4[qq];
                ac0 = fmaf(hq.x, wq.x, ac0);
                ac1 = fmaf(hq.y, wq.y, ac1);
                ac2 = fmaf(hq.z, wq.z, ac2);
                ac3 = fmaf(hq.w, wq.w, ac3);
            }
            float yv = (ac0 + ac1) + (ac2 + ac3);
            out[rowx + s * NB_] = yv;
            if (s <= T_IN_) {
                sX[yn * 12 + yb] = xreg;                       // teacher input x[:,s]
                if (s + 1 <= T_IN_) xreg = x[rowx + (s + 1) * NB_];
            } else {
                sX[yn * 12 + yb] = yv;                         // autoregressive feedback
            }
        }

        // ---- h-GEMM: this kg's 32 k-rows, all 4 gates of dim d ----
        ull A[4][4];
        #pragma unroll
        for (int g = 0; g < 4; g++)
            #pragma unroll
            for (int p = 0; p < 4; p++) A[g][p] = 0ull;

        // issue first 7 streamed rows
        float4 buf[7];
        #pragma unroll
        for (int u = 0; u < 7; u++) buf[u] = __ldg(gp4 + u * 128);

        // 18 resident rows
        #pragma unroll 1
        for (int c = 0; c < 6; c++) {
            #pragma unroll
            for (int u = 0; u < 3; u++) {
                int i = c * 3 + u;
                float4 wq = *(const float4*)(swb + i * 512);
                do_k4(myH + i * 32, wq, A);
            }
        }
        // 14 streamed rows: consume 7 + refill, then consume 7
        #pragma unroll
        for (int u = 0; u < 7; u++) {
            float4 wq = buf[u];
            buf[u] = __ldg(gp4 + (7 + u) * 128);
            do_k4(myH + (18 + u) * 32, wq, A);
        }
        #pragma unroll
        for (int u = 0; u < 7; u++)
            do_k4(myH + (25 + u) * 32, buf[u], A);

        __syncthreads();   // B1: sX ready; all h reads complete

        // ---- x-part: this kg's n-subset ----
        #pragma unroll
        for (int m = 0; m < 4; m++) {
            if (m < ncnt) {
                ull x01, x23, x45, x67;
                lds_v2u64(x01, x23, xbb + (nbase + m) * 48);
                lds_v2u64(x45, x67, xbb + (nbase + m) * 48 + 16);
                ull wi = pk2(wxq[m].x), wf = pk2(wxq[m].y), wg = pk2(wxq[m].z), wo = pk2(wxq[m].w);
                fma2(A[0][0], x01, wi); fma2(A[0][1], x23, wi); fma2(A[0][2], x45, wi); fma2(A[0][3], x67, wi);
                fma2(A[1][0], x01, wf); fma2(A[1][1], x23, wf); fma2(A[1][2], x45, wf); fma2(A[1][3], x67, wf);
                fma2(A[2][0], x01, wg); fma2(A[2][1], x23, wg); fma2(A[2][2], x45, wg); fma2(A[2][3], x67, wg);
                fma2(A[3][0], x01, wo); fma2(A[3][1], x23, wo); fma2(A[3][2], x45, wo); fma2(A[3][3], x67, wo);
            }
        }

        // ---- publish partials for pairs p != kg : P[p][kg][g][d] ----
        #pragma unroll
        for (int p = 0; p < 4; p++) {
            if (p != kg) {
                #pragma unroll
                for (int g = 0; g < 4; g++)
                    sts_u64(Pb + (unsigned)((((p * 4 + kg) * 4 + g) * 128 + d) * 8), A[g][p]);
            }
        }
        __syncthreads();   // B2: partials ready

        // ---- update: dim d, batch pair q = kg ----
        {
            ull S[4];
            #pragma unroll
            for (int g = 0; g < 4; g++) S[g] = A[g][kg];
            #pragma unroll
            for (int o = 1; o < 4; o++) {
                int src = kg ^ o;   // covers all kg' != kg
                #pragma unroll
                for (int g = 0; g < 4; g++)
                    S[g] = S[g], add2(S[g], lds_u64(Pb + (unsigned)((((kg * 4 + src) * 4 + g) * 128 + d) * 8)));
            }
            add2(S[0], pk2(bv.x));
            add2(S[1], pk2(bv.y));
            add2(S[2], pk2(bv.z));
            add2(S[3], pk2(bv.w));

            float i0 = sigm(lo2(S[0])), i1 = sigm(hi2(S[0]));
            float f0 = sigm(lo2(S[1])), f1 = sigm(hi2(S[1]));
            float g0 = tanh_(lo2(S[2])), g1 = tanh_(hi2(S[2]));
            float o0 = sigm(lo2(S[3])), o1 = sigm(hi2(S[3]));
            float c0 = fmaf(f0, cc0, i0 * g0);
            float c1 = fmaf(f1, cc1, i1 * g1);
            cc0 = c0; cc1 = c1;
            float h0 = o0 * tanh_(c0);
            float h1 = o1 * tanh_(c1);

            sts_u64(hb + (unsigned)(d * 32 + kg * 8), pack2(h0, h1));  // k-major for GEMM
            sHT[(2 * kg) * 132 + d]     = h0;                          // transposed for readout
            sHT[(2 * kg + 1) * 132 + d] = h1;
        }
        __syncthreads();   // B3: h ready for next step
    }

    // ---- final readout: y_127 ----
    if (yth) {
        const float4* h4 = (const float4*)(sHT + yb * 132);
        const float4* w4 = (const float4*)(sWo + yn * 132);
        float ac0 = bo, ac1 = 0.0f, ac2 = 0.0f, ac3 = 0.0f;
        #pragma unroll 8
        for (int qq = 0; qq < 32; qq++) {
            float4 hq = h4[qq];
            float4 wq = w4[qq];
            ac0 = fmaf(hq.x, wq.x, ac0);
            ac1 = fmaf(hq.y, wq.y, ac1);
            ac2 = fmaf(hq.z, wq.z, ac2);
            ac3 = fmaf(hq.w, wq.w, ac3);
        }
        out[rowx + (T_SEQ - 1) * NB_] = (ac0 + ac1) + (ac2 + ac3);
    }
}

extern "C" void kernel_launch(void* const* d_in, const int* in_sizes, int n_in,
                              void* d_out, int out_size)
{
    const float* x     = (const float*)d_in[0];
    const float* W_ih  = (const float*)d_in[1];
    const float* W_hh  = (const float*)d_in[2];
    const float* b_ih  = (const float*)d_in[3];
    const float* b_hh  = (const float*)d_in[4];
    const float* W_out = (const float*)d_in[5];
    const float* b_out = (const float*)d_in[6];
    float* out = (float*)d_out;

    cudaFuncSetAttribute(lstm_main, cudaFuncAttributeMaxDynamicSharedMemorySize, SMEM_BYTES);

    prep_kernel<<<256, 256>>>(W_hh, W_ih, b_ih, b_hh);
    lstm_main<<<NBLOCKS, NTHREADS, SMEM_BYTES>>>(x, W_out, b_out, out);
}

// round 10
// speedup vs baseline: 1.5519x; 1.5519x over previous
#include <cuda_runtime.h>

#define T_SEQ   128
#define NB_     13
#define T_IN_   64
#define BQ      8
#define NBLOCKS 128
#define NTHREADS 512

// ---- shared memory layout (float indices) ----
#define SW_OFF   0        // [88][512] quad-interleaved W_hh; slabrow r = quarter*22+i <-> k = kg*64+khalf*32+i
#define SP_OFF   45056    // partials: 4096 u64 (8192 floats), R8 slot scheme
#define SH_OFF   53248    // padded h: addr = k*32 + (k>>5)*16 + pair*8 ; 1040 floats
#define SHT_OFF  54288    // [8][132] h transposed (readout)
#define SWO_OFF  55344    // [13][132] W_out padded
#define SX_OFF   57060    // [13][12] x_t (48B row stride)
#define SMEM_FLOATS 57216
#define SMEM_BYTES  (SMEM_FLOATS * 4)   // 228864 <= 232448

// quad-interleaved: g_W4[k*512 + d*4 + g] = W_hh[(d+128g)*128 + k]
__device__ float g_W4[128 * 512];
__device__ float g_Wih4[NB_ * 512];   // g_Wih4[n*512 + d*4 + g] = W_ih[(d+128g)*13 + n]
__device__ float g_bias4[512];        // g_bias4[d*4+g] = (b_ih+b_hh)[d+128g]

typedef unsigned long long ull;

// ---------- helpers ----------
__device__ __forceinline__ unsigned sptr(const void* p) {
    return (unsigned)__cvta_generic_to_shared(p);
}
__device__ __forceinline__ ull pk2(float v) {
    ull r; unsigned u = __float_as_uint(v);
    asm("mov.b64 %0, {%1, %1};" : "=l"(r) : "r"(u));
    return r;
}
__device__ __forceinline__ ull pack2(float lo, float hi) {
    ull r;
    asm("mov.b64 %0, {%1, %2};" : "=l"(r) : "r"(__float_as_uint(lo)), "r"(__float_as_uint(hi)));
    return r;
}
__device__ __forceinline__ void fma2(ull& a, ull b, ull c) {
    asm("fma.rn.f32x2 %0, %1, %2, %0;" : "+l"(a) : "l"(b), "l"(c));
}
__device__ __forceinline__ void add2(ull& a, ull b) {
    asm("add.rn.f32x2 %0, %0, %1;" : "+l"(a) : "l"(b));
}
__device__ __forceinline__ void lds_v2u64(ull& a, ull& b, unsigned addr) {
    asm volatile("ld.shared.v2.u64 {%0, %1}, [%2];" : "=l"(a), "=l"(b) : "r"(addr));
}
__device__ __forceinline__ ull lds_u64(unsigned addr) {
    ull v;
    asm volatile("ld.shared.b64 %0, [%1];" : "=l"(v) : "r"(addr));
    return v;
}
__device__ __forceinline__ void sts_u64(unsigned addr, ull v) {
    asm volatile("st.shared.b64 [%0], %1;" :: "r"(addr), "l"(v) : "memory");
}
__device__ __forceinline__ float lo2(ull a) { return __uint_as_float((unsigned)(a & 0xffffffffull)); }
__device__ __forceinline__ float hi2(ull a) { return __uint_as_float((unsigned)(a >> 32)); }
__device__ __forceinline__ float sigm(float v) { return __fdividef(1.0f, 1.0f + __expf(-v)); }
__device__ __forceinline__ float tanh_(float v) { return __fdividef(2.0f, 1.0f + __expf(-2.0f * v)) - 1.0f; }

// one k, all 4 gates of dim d, 8 batch: 2 LDS.128 + 16 fma2
__device__ __forceinline__ void do_k4(unsigned haddr, float4 wq, ull (&A)[4][4])
{
    ull h01, h23, h45, h67;
    lds_v2u64(h01, h23, haddr);
    lds_v2u64(h45, h67, haddr + 16);
    ull wi = pk2(wq.x), wf = pk2(wq.y), wg = pk2(wq.z), wo = pk2(wq.w);
    fma2(A[0][0], h01, wi); fma2(A[0][1], h23, wi); fma2(A[0][2], h45, wi); fma2(A[0][3], h67, wi);
    fma2(A[1][0], h01, wf); fma2(A[1][1], h23, wf); fma2(A[1][2], h45, wf); fma2(A[1][3], h67, wf);
    fma2(A[2][0], h01, wg); fma2(A[2][1], h23, wg); fma2(A[2][2], h45, wg); fma2(A[2][3], h67, wg);
    fma2(A[3][0], h01, wo); fma2(A[3][1], h23, wo); fma2(A[3][2], h45, wo); fma2(A[3][3], h67, wo);
}

// ---------- prep ----------
__global__ void prep_kernel(const float* __restrict__ W_hh,
                            const float* __restrict__ W_ih,
                            const float* __restrict__ b_ih,
                            const float* __restrict__ b_hh)
{
    int idx = blockIdx.x * blockDim.x + threadIdx.x;
    if (idx < 128 * 512) {
        int k = idx >> 9, r = idx & 511;
        int d = r >> 2, g = r & 3;
        g_W4[idx] = W_hh[(d + 128 * g) * 128 + k];
    }
    if (idx < NB_ * 512) {
        int n = idx >> 9, r = idx & 511;
        int d = r >> 2, g = r & 3;
        g_Wih4[idx] = W_ih[(d + 128 * g) * NB_ + n];
    }
    if (idx < 512) {
        int d = idx >> 2, g = idx & 3;
        g_bias4[idx] = b_ih[d + 128 * g] + b_hh[d + 128 * g];
    }
}

// ---------- main persistent LSTM kernel ----------
__global__ void __launch_bounds__(NTHREADS, 1)
lstm_main(const float* __restrict__ x, const float* __restrict__ W_out,
          const float* __restrict__ b_out, float* __restrict__ out)
{
    extern __shared__ float sm[];
    float* sW  = sm + SW_OFF;
    float* sH  = sm + SH_OFF;
    float* sHT = sm + SHT_OFF;
    float* sWo = sm + SWO_OFF;
    float* sX  = sm + SX_OFF;

    const int t     = threadIdx.x;
    const int kg    = t >> 8;                       // k-half (0/1)
    const int khalf = (t >> 4) & 1;                 // k-quarter within half (lane^16 partner)
    const int d     = ((t >> 5) & 7) * 16 + (t & 15);  // 0..127
    const int quarter = kg * 2 + khalf;             // 0..3
    const int b0 = blockIdx.x * BQ;

    // ---- cooperative smem fill ----
    {
        const float4* src = (const float4*)g_W4;
        float4* dst = (float4*)sW;
        for (int i = t; i < 88 * 128; i += NTHREADS) {
            int r = i >> 7, c = i & 127;
            int qr = r / 22, ri = r - qr * 22;
            int k = (qr >> 1) * 64 + (qr & 1) * 32 + ri;
            dst[i] = src[k * 128 + c];
        }
        for (int i = t; i < NB_ * 128; i += NTHREADS) {
            int n = i >> 7, dd = i & 127;
            sWo[n * 132 + dd] = W_out[i];
        }
        for (int i = t; i < 1040; i += NTHREADS) sH[i] = 0.0f;
    }

    const unsigned hb  = sptr(sH);
    const unsigned xbb = sptr(sX);
    const unsigned Pb  = sptr(sm + SP_OFF);

    // per-quarter pointers
    const int k0 = kg * 64 + khalf * 32;
    const float* swb = sW + (quarter * 22) * 512 + d * 4;               // 22 resident rows
    const float4* gp4 = ((const float4*)g_W4) + (k0 + 22) * 128 + d;    // 10 streamed rows
    const unsigned myH = hb + (unsigned)(k0 * 32 + (k0 >> 5) * 16);     // padded h base

    // x-part: quarter n-split 4/3/3/3
    const int nbase = (quarter == 0) ? 0 : (quarter == 1 ? 4 : (quarter == 2 ? 7 : 10));
    const int ncnt  = (quarter == 0) ? 4 : 3;
    float4 wxq[4];
    #pragma unroll
    for (int m = 0; m < 4; m++)
        if (m < ncnt) wxq[m] = __ldg(((const float4*)g_Wih4) + (nbase + m) * 128 + d);

    // bias folded into quarter-0 accumulator init
    float4 bv = make_float4(0.f, 0.f, 0.f, 0.f);
    if (quarter == 0) bv = __ldg(((const float4*)g_bias4) + d);

    // update identity: dim du, batch-pair q
    const int du = t & 127;
    const int q  = t >> 7;          // 0..3
    float cc0 = 0.0f, cc1 = 0.0f;

    // readout mapping (threads 0..103)
    const int yb = t / NB_;
    const int yn = t - yb * NB_;
    const bool yth = (t < BQ * NB_);
    const float bo = yth ? __ldg(b_out + yn) : 0.0f;
    const int rowx = yth ? ((b0 + yb) * (T_SEQ * NB_) + yn) : 0;

    float xreg = 0.0f;
    if (yth) {
        float x0 = x[rowx];
        sX[yn * 12 + yb] = x0;
        out[rowx] = x0;                  // out[:,0] = x[:,0]
        xreg = x[rowx + NB_];            // prefetch x[:,1]
    }
    __syncthreads();

    for (int s = 0; s < T_SEQ - 1; s++) {
        // ---- hidden readout of y_s (concurrent with h-GEMM) ----
        if (s > 0 && yth) {
            const float4* h4 = (const float4*)(sHT + yb * 132);
            const float4* w4 = (const float4*)(sWo + yn * 132);
            float ac0 = bo, ac1 = 0.0f, ac2 = 0.0f, ac3 = 0.0f;
            #pragma unroll 8
            for (int qq = 0; qq < 32; qq++) {
                float4 hq = h4[qq];
                float4 wq = w4[qq];
                ac0 = fmaf(hq.x, wq.x, ac0);
                ac1 = fmaf(hq.y, wq.y, ac1);
                ac2 = fmaf(hq.z, wq.z, ac2);
                ac3 = fmaf(hq.w, wq.w, ac3);
            }
            float yv = (ac0 + ac1) + (ac2 + ac3);
            out[rowx + s * NB_] = yv;
            if (s <= T_IN_) {
                sX[yn * 12 + yb] = xreg;                       // teacher input x[:,s]
                if (s + 1 <= T_IN_) xreg = x[rowx + (s + 1) * NB_];
            } else {
                sX[yn * 12 + yb] = yv;                         // autoregressive feedback
            }
        }

        // ---- h-GEMM: this quarter's 32 k-rows, all 4 gates of dim d ----
        ull A[4][4];
        {
            ull bi = pk2(bv.x), bf = pk2(bv.y), bg = pk2(bv.z), bo2 = pk2(bv.w);
            A[0][0] = bi; A[0][1] = bi; A[0][2] = bi; A[0][3] = bi;
            A[1][0] = bf; A[1][1] = bf; A[1][2] = bf; A[1][3] = bf;
            A[2][0] = bg; A[2][1] = bg; A[2][2] = bg; A[2][3] = bg;
            A[3][0] = bo2; A[3][1] = bo2; A[3][2] = bo2; A[3][3] = bo2;
        }
        // issue 5 streamed rows
        float4 buf[5];
        #pragma unroll
        for (int u = 0; u < 5; u++) buf[u] = __ldg(gp4 + u * 128);

        // 22 resident rows
        #pragma unroll 1
        for (int c = 0; c < 2; c++) {
            #pragma unroll
            for (int u = 0; u < 11; u++) {
                int i = c * 11 + u;
                float4 wq = *(const float4*)(swb + i * 512);
                do_k4(myH + i * 32, wq, A);
            }
        }
        // 10 streamed rows: consume 5 + refill, then consume 5
        #pragma unroll
        for (int u = 0; u < 5; u++) {
            float4 wq = buf[u];
            buf[u] = __ldg(gp4 + (5 + u) * 128);
            do_k4(myH + (22 + u) * 32, wq, A);
        }
        #pragma unroll
        for (int u = 0; u < 5; u++)
            do_k4(myH + (27 + u) * 32, buf[u], A);

        __syncthreads();   // B1: sX ready; all h reads complete

        // ---- x-part: this quarter's n-subset ----
        #pragma unroll
        for (int m = 0; m < 4; m++) {
            if (m < ncnt) {
                ull x01, x23, x45, x67;
                lds_v2u64(x01, x23, xbb + (nbase + m) * 48);
                lds_v2u64(x45, x67, xbb + (nbase + m) * 48 + 16);
                ull wi = pk2(wxq[m].x), wf = pk2(wxq[m].y), wg = pk2(wxq[m].z), wo = pk2(wxq[m].w);
                fma2(A[0][0], x01, wi); fma2(A[0][1], x23, wi); fma2(A[0][2], x45, wi); fma2(A[0][3], x67, wi);
                fma2(A[1][0], x01, wf); fma2(A[1][1], x23, wf); fma2(A[1][2], x45, wf); fma2(A[1][3], x67, wf);
                fma2(A[2][0], x01, wg); fma2(A[2][1], x23, wg); fma2(A[2][2], x45, wg); fma2(A[2][3], x67, wg);
                fma2(A[3][0], x01, wo); fma2(A[3][1], x23, wo); fma2(A[3][2], x45, wo); fma2(A[3][3], x67, wo);
            }
        }

        // ---- lane-pair combine: partner = lane^16 (other k-quarter, same d/kg) ----
        #pragma unroll
        for (int g = 0; g < 4; g++)
            #pragma unroll
            for (int p = 0; p < 4; p++)
                add2(A[g][p], __shfl_xor_sync(0xFFFFFFFFu, A[g][p], 16, 32));

        // ---- publish (khalf0 lanes only) into R8 slot scheme ----
        if (khalf == 0) {
            #pragma unroll
            for (int p = 0; p < 4; p++) {
                sts_u64(Pb + (unsigned)((((p * 2 + kg) * 256) + d) * 8),        A[0][p]);  // i: row d
                sts_u64(Pb + (unsigned)((((p * 2 + kg) * 256) + d + 128) * 8),  A[1][p]);  // f: row d+128
                sts_u64(Pb + (unsigned)(((((4 + p) * 2 + kg) * 256) + d) * 8),       A[2][p]);  // g
                sts_u64(Pb + (unsigned)(((((4 + p) * 2 + kg) * 256) + d + 128) * 8), A[3][p]);  // o
            }
        }
        __syncthreads();   // B2: partials ready

        // ---- update (all 512 threads): dim du, batch pair q ----
        {
            ull Ai = lds_u64(Pb + (unsigned)(((q * 2 + 0) * 256 + du) * 8));
            add2(Ai,  lds_u64(Pb + (unsigned)(((q * 2 + 1) * 256 + du) * 8)));
            ull Af = lds_u64(Pb + (unsigned)(((q * 2 + 0) * 256 + du + 128) * 8));
            add2(Af,  lds_u64(Pb + (unsigned)(((q * 2 + 1) * 256 + du + 128) * 8)));
            ull Ag = lds_u64(Pb + (unsigned)((((4 + q) * 2 + 0) * 256 + du) * 8));
            add2(Ag,  lds_u64(Pb + (unsigned)((((4 + q) * 2 + 1) * 256 + du) * 8)));
            ull Ao = lds_u64(Pb + (unsigned)((((4 + q) * 2 + 0) * 256 + du + 128) * 8));
            add2(Ao,  lds_u64(Pb + (unsigned)((((4 + q) * 2 + 1) * 256 + du + 128) * 8)));

            float i0 = sigm(lo2(Ai)), i1 = sigm(hi2(Ai));
            float f0 = sigm(lo2(Af)), f1 = sigm(hi2(Af));
            float g0 = tanh_(lo2(Ag)), g1 = tanh_(hi2(Ag));
            float o0 = sigm(lo2(Ao)), o1 = sigm(hi2(Ao));
            float c0 = fmaf(f0, cc0, i0 * g0);
            float c1 = fmaf(f1, cc1, i1 * g1);
            cc0 = c0; cc1 = c1;
            float h0 = o0 * tanh_(c0);
            float h1 = o1 * tanh_(c1);

            // padded k-major h + transposed copy
            sts_u64(hb + (unsigned)(du * 32 + (du >> 5) * 16 + q * 8), pack2(h0, h1));
            sHT[(2 * q) * 132 + du]     = h0;
            sHT[(2 * q + 1) * 132 + du] = h1;
        }
        __syncthreads();   // B3: h ready for next step
    }

    // ---- final readout: y_127 ----
    if (yth) {
        const float4* h4 = (const float4*)(sHT + yb * 132);
        const float4* w4 = (const float4*)(sWo + yn * 132);
        float ac0 = bo, ac1 = 0.0f, ac2 = 0.0f, ac3 = 0.0f;
        #pragma unroll 8
        for (int qq = 0; qq < 32; qq++) {
            float4 hq = h4[qq];
            float4 wq = w4[qq];
            ac0 = fmaf(hq.x, wq.x, ac0);
            ac1 = fmaf(hq.y, wq.y, ac1);
            ac2 = fmaf(hq.z, wq.z, ac2);
            ac3 = fmaf(hq.w, wq.w, ac3);
        }
        out[rowx + (T_SEQ - 1) * NB_] = (ac0 + ac1) + (ac2 + ac3);
    }
}

extern "C" void kernel_launch(void* const* d_in, const int* in_sizes, int n_in,
                              void* d_out, int out_size)
{
    const float* x     = (const float*)d_in[0];
    const float* W_ih  = (const float*)d_in[1];
    const float* W_hh  = (const float*)d_in[2];
    const float* b_ih  = (const float*)d_in[3];
    const float* b_hh  = (const float*)d_in[4];
    const float* W_out = (const float*)d_in[5];
    const float* b_out = (const float*)d_in[6];
    float* out = (float*)d_out;

    cudaFuncSetAttribute(lstm_main, cudaFuncAttributeMaxDynamicSharedMemorySize, SMEM_BYTES);

    prep_kernel<<<256, 256>>>(W_hh, W_ih, b_ih, b_hh);
    lstm_main<<<NBLOCKS, NTHREADS, SMEM_BYTES>>>(x, W_out, b_out, out);
}

// round 12
// speedup vs baseline: 1.6090x; 1.0367x over previous
#include <cuda_runtime.h>

#define T_SEQ   128
#define NB_     13
#define T_IN_   64
#define BQ      8
#define NBLOCKS 128
#define NTHREADS 512

// ---- shared memory layout (float indices) ----
#define SW_OFF   0        // [88][512] quad-interleaved W_hh; slabrow r = quarter*22+i <-> k = kg*64+khalf*32+i
#define SP_OFF   45056    // partials: 4096 u64 (8192 floats), R8 slot scheme
#define SH_OFF   53248    // padded h: addr = k*32 + (k>>5)*16 + pair*8 ; 1040 floats
#define SHT_OFF  54288    // [8][132] h transposed (readout)
#define SWO_OFF  55344    // [13][132] W_out padded
#define SX_OFF   57060    // [13][12] x_t (48B row stride)
#define SMEM_FLOATS 57216
#define SMEM_BYTES  (SMEM_FLOATS * 4)   // 228864 <= 232448

// quad-interleaved: g_W4[k*512 + d*4 + g] = W_hh[(d+128g)*128 + k]
__device__ float g_W4[128 * 512];
__device__ float g_Wih4[NB_ * 512];   // g_Wih4[n*512 + d*4 + g] = W_ih[(d+128g)*13 + n]
__device__ float g_bias4[512];        // g_bias4[d*4+g] = (b_ih+b_hh)[d+128g]

typedef unsigned long long ull;

// ---------- helpers ----------
__device__ __forceinline__ unsigned sptr(const void* p) {
    return (unsigned)__cvta_generic_to_shared(p);
}
__device__ __forceinline__ ull pk2(float v) {
    ull r; unsigned u = __float_as_uint(v);
    asm("mov.b64 %0, {%1, %1};" : "=l"(r) : "r"(u));
    return r;
}
__device__ __forceinline__ ull pack2(float lo, float hi) {
    ull r;
    asm("mov.b64 %0, {%1, %2};" : "=l"(r) : "r"(__float_as_uint(lo)), "r"(__float_as_uint(hi)));
    return r;
}
__device__ __forceinline__ void fma2(ull& a, ull b, ull c) {
    asm("fma.rn.f32x2 %0, %1, %2, %0;" : "+l"(a) : "l"(b), "l"(c));
}
__device__ __forceinline__ void add2(ull& a, ull b) {
    asm("add.rn.f32x2 %0, %0, %1;" : "+l"(a) : "l"(b));
}
__device__ __forceinline__ void lds_v2u64(ull& a, ull& b, unsigned addr) {
    asm volatile("ld.shared.v2.u64 {%0, %1}, [%2];" : "=l"(a), "=l"(b) : "r"(addr));
}
__device__ __forceinline__ ull lds_u64(unsigned addr) {
    ull v;
    asm volatile("ld.shared.b64 %0, [%1];" : "=l"(v) : "r"(addr));
    return v;
}
__device__ __forceinline__ void sts_u64(unsigned addr, ull v) {
    asm volatile("st.shared.b64 [%0], %1;" :: "r"(addr), "l"(v) : "memory");
}
__device__ __forceinline__ float lo2(ull a) { return __uint_as_float((unsigned)(a & 0xffffffffull)); }
__device__ __forceinline__ float hi2(ull a) { return __uint_as_float((unsigned)(a >> 32)); }

// HW tanh (sm_75+): abs err ~1e-4, plenty inside the 1e-3 gate budget
__device__ __forceinline__ float tanhax(float v) {
    float r;
    asm("tanh.approx.f32 %0, %1;" : "=f"(r) : "f"(v));
    return r;
}
__device__ __forceinline__ float sigm(float v) { return fmaf(0.5f, tanhax(0.5f * v), 0.5f); }
__device__ __forceinline__ float tanh_(float v) { return tanhax(v); }

// one k, all 4 gates of dim d, 8 batch: 2 LDS.128 + 16 fma2
__device__ __forceinline__ void do_k4(unsigned haddr, float4 wq, ull (&A)[4][4])
{
    ull h01, h23, h45, h67;
    lds_v2u64(h01, h23, haddr);
    lds_v2u64(h45, h67, haddr + 16);
    ull wi = pk2(wq.x), wf = pk2(wq.y), wg = pk2(wq.z), wo = pk2(wq.w);
    fma2(A[0][0], h01, wi); fma2(A[0][1], h23, wi); fma2(A[0][2], h45, wi); fma2(A[0][3], h67, wi);
    fma2(A[1][0], h01, wf); fma2(A[1][1], h23, wf); fma2(A[1][2], h45, wf); fma2(A[1][3], h67, wf);
    fma2(A[2][0], h01, wg); fma2(A[2][1], h23, wg); fma2(A[2][2], h45, wg); fma2(A[2][3], h67, wg);
    fma2(A[3][0], h01, wo); fma2(A[3][1], h23, wo); fma2(A[3][2], h45, wo); fma2(A[3][3], h67, wo);
}

// ---------- prep ----------
__global__ void prep_kernel(const float* __restrict__ W_hh,
                            const float* __restrict__ W_ih,
                            const float* __restrict__ b_ih,
                            const float* __restrict__ b_hh)
{
    int idx = blockIdx.x * blockDim.x + threadIdx.x;
    if (idx < 128 * 512) {
        int k = idx >> 9, r = idx & 511;
        int d = r >> 2, g = r & 3;
        g_W4[idx] = W_hh[(d + 128 * g) * 128 + k];
    }
    if (idx < NB_ * 512) {
        int n = idx >> 9, r = idx & 511;
        int d = r >> 2, g = r & 3;
        g_Wih4[idx] = W_ih[(d + 128 * g) * NB_ + n];
    }
    if (idx < 512) {
        int d = idx >> 2, g = idx & 3;
        g_bias4[idx] = b_ih[d + 128 * g] + b_hh[d + 128 * g];
    }
}

// ---------- main persistent LSTM kernel ----------
__global__ void __launch_bounds__(NTHREADS, 1)
lstm_main(const float* __restrict__ x, const float* __restrict__ W_out,
          const float* __restrict__ b_out, float* __restrict__ out)
{
    extern __shared__ float sm[];
    float* sW  = sm + SW_OFF;
    float* sH  = sm + SH_OFF;
    float* sHT = sm + SHT_OFF;
    float* sWo = sm + SWO_OFF;
    float* sX  = sm + SX_OFF;

    const int t     = threadIdx.x;
    const int kg    = t >> 8;                       // k-half (0/1)
    const int khalf = (t >> 4) & 1;                 // k-quarter within half (lane^16 partner)
    const int d     = ((t >> 5) & 7) * 16 + (t & 15);  // 0..127
    const int quarter = kg * 2 + khalf;             // 0..3
    const int b0 = blockIdx.x * BQ;

    // ---- cooperative smem fill ----
    {
        const float4* src = (const float4*)g_W4;
        float4* dst = (float4*)sW;
        for (int i = t; i < 88 * 128; i += NTHREADS) {
            int r = i >> 7, c = i & 127;
            int qr = r / 22, ri = r - qr * 22;
            int k = (qr >> 1) * 64 + (qr & 1) * 32 + ri;
            dst[i] = src[k * 128 + c];
        }
        for (int i = t; i < NB_ * 128; i += NTHREADS) {
            int n = i >> 7, dd = i & 127;
            sWo[n * 132 + dd] = W_out[i];
        }
        for (int i = t; i < 1040; i += NTHREADS) sH[i] = 0.0f;
    }

    const unsigned hb  = sptr(sH);
    const unsigned xbb = sptr(sX);
    const unsigned Pb  = sptr(sm + SP_OFF);

    // per-quarter pointers
    const int k0 = kg * 64 + khalf * 32;
    const float* swb = sW + (quarter * 22) * 512 + d * 4;               // 22 resident rows
    const float4* gp4 = ((const float4*)g_W4) + (k0 + 22) * 128 + d;    // 10 streamed rows
    const unsigned myH = hb + (unsigned)(k0 * 32 + (k0 >> 5) * 16);     // padded h base

    // x-part: quarter n-split 4/4/3/2 (readout-hosting warps 12-15 = quarters 2/3 are lightest)
    const int nbase = (quarter == 0) ? 0 : (quarter == 1 ? 4 : (quarter == 2 ? 8 : 11));
    const int ncnt  = (quarter == 0) ? 4 : (quarter == 1 ? 4 : (quarter == 2 ? 3 : 2));
    float4 wxq[4];
    #pragma unroll
    for (int m = 0; m < 4; m++)
        if (m < ncnt) wxq[m] = __ldg(((const float4*)g_Wih4) + (nbase + m) * 128 + d);

    // bias folded into quarter-0 accumulator init
    float4 bv = make_float4(0.f, 0.f, 0.f, 0.f);
    if (quarter == 0) bv = __ldg(((const float4*)g_bias4) + d);

    // update identity: dim du, batch-pair q
    const int du = t & 127;
    const int q  = t >> 7;          // 0..3
    float cc0 = 0.0f, cc1 = 0.0f;

    // readout mapping: threads 384..487 (warps 12-15)
    const int yi = t - 384;
    const bool yth = (yi >= 0) && (yi < BQ * NB_);
    const int yb = yth ? (yi / NB_) : 0;
    const int yn = yth ? (yi - yb * NB_) : 0;
    const float bo = yth ? __ldg(b_out + yn) : 0.0f;
    const int rowx = yth ? ((b0 + yb) * (T_SEQ * NB_) + yn) : 0;

    float xreg = 0.0f;
    if (yth) {
        float x0 = x[rowx];
        sX[yn * 12 + yb] = x0;
        out[rowx] = x0;                  // out[:,0] = x[:,0]
        xreg = x[rowx + NB_];            // prefetch x[:,1]
    }
    __syncthreads();

    for (int s = 0; s < T_SEQ - 1; s++) {
        // ---- hidden readout of y_s (concurrent with h-GEMM) ----
        if (s > 0 && yth) {
            const float4* h4 = (const float4*)(sHT + yb * 132);
            const float4* w4 = (const float4*)(sWo + yn * 132);
            float ac0 = bo, ac1 = 0.0f, ac2 = 0.0f, ac3 = 0.0f;
            #pragma unroll 8
            for (int qq = 0; qq < 32; qq++) {
                float4 hq = h4[qq];
                float4 wq = w4[qq];
                ac0 = fmaf(hq.x, wq.x, ac0);
                ac1 = fmaf(hq.y, wq.y, ac1);
                ac2 = fmaf(hq.z, wq.z, ac2);
                ac3 = fmaf(hq.w, wq.w, ac3);
            }
            float yv = (ac0 + ac1) + (ac2 + ac3);
            out[rowx + s * NB_] = yv;
            if (s <= T_IN_) {
                sX[yn * 12 + yb] = xreg;                       // teacher input x[:,s]
                if (s + 1 <= T_IN_) xreg = x[rowx + (s + 1) * NB_];
            } else {
                sX[yn * 12 + yb] = yv;                         // autoregressive feedback
            }
        }

        // ---- h-GEMM: this quarter's 32 k-rows, all 4 gates of dim d ----
        ull A[4][4];
        {
            ull bi = pk2(bv.x), bf = pk2(bv.y), bg = pk2(bv.z), bo2 = pk2(bv.w);
            A[0][0] = bi; A[0][1] = bi; A[0][2] = bi; A[0][3] = bi;
            A[1][0] = bf; A[1][1] = bf; A[1][2] = bf; A[1][3] = bf;
            A[2][0] = bg; A[2][1] = bg; A[2][2] = bg; A[2][3] = bg;
            A[3][0] = bo2; A[3][1] = bo2; A[3][2] = bo2; A[3][3] = bo2;
        }
        // issue 5 streamed rows
        float4 buf[5];
        #pragma unroll
        for (int u = 0; u < 5; u++) buf[u] = __ldg(gp4 + u * 128);

        // 22 resident rows
        #pragma unroll 1
        for (int c = 0; c < 2; c++) {
            #pragma unroll
            for (int u = 0; u < 11; u++) {
                int i = c * 11 + u;
                float4 wq = *(const float4*)(swb + i * 512);
                do_k4(myH + i * 32, wq, A);
            }
        }
        // 10 streamed rows: consume 5 + refill, then consume 5
        #pragma unroll
        for (int u = 0; u < 5; u++) {
            float4 wq = buf[u];
            buf[u] = __ldg(gp4 + (5 + u) * 128);
            do_k4(myH + (22 + u) * 32, wq, A);
        }
        #pragma unroll
        for (int u = 0; u < 5; u++)
            do_k4(myH + (27 + u) * 32, buf[u], A);

        __syncthreads();   // B1: sX ready; all h reads complete

        // ---- x-part: this quarter's n-subset ----
        #pragma unroll
        for (int m = 0; m < 4; m++) {
            if (m < ncnt) {
                ull x01, x23, x45, x67;
                lds_v2u64(x01, x23, xbb + (nbase + m) * 48);
                lds_v2u64(x45, x67, xbb + (nbase + m) * 48 + 16);
                ull wi = pk2(wxq[m].x), wf = pk2(wxq[m].y), wg = pk2(wxq[m].z), wo = pk2(wxq[m].w);
                fma2(A[0][0], x01, wi); fma2(A[0][1], x23, wi); fma2(A[0][2], x45, wi); fma2(A[0][3], x67, wi);
                fma2(A[1][0], x01, wf); fma2(A[1][1], x23, wf); fma2(A[1][2], x45, wf); fma2(A[1][3], x67, wf);
                fma2(A[2][0], x01, wg); fma2(A[2][1], x23, wg); fma2(A[2][2], x45, wg); fma2(A[2][3], x67, wg);
                fma2(A[3][0], x01, wo); fma2(A[3][1], x23, wo); fma2(A[3][2], x45, wo); fma2(A[3][3], x67, wo);
            }
        }

        // ---- lane-pair combine: partner = lane^16 (other k-quarter, same d/kg) ----
        #pragma unroll
        for (int g = 0; g < 4; g++)
            #pragma unroll
            for (int p = 0; p < 4; p++)
                add2(A[g][p], __shfl_xor_sync(0xFFFFFFFFu, A[g][p], 16, 32));

        // ---- publish (khalf0 lanes only) into R8 slot scheme ----
        if (khalf == 0) {
            #pragma unroll
            for (int p = 0; p < 4; p++) {
                sts_u64(Pb + (unsigned)((((p * 2 + kg) * 256) + d) * 8),        A[0][p]);  // i: row d
                sts_u64(Pb + (unsigned)((((p * 2 + kg) * 256) + d + 128) * 8),  A[1][p]);  // f: row d+128
                sts_u64(Pb + (unsigned)(((((4 + p) * 2 + kg) * 256) + d) * 8),       A[2][p]);  // g
                sts_u64(Pb + (unsigned)(((((4 + p) * 2 + kg) * 256) + d + 128) * 8), A[3][p]);  // o
            }
        }
        __syncthreads();   // B2: partials ready

        // ---- update (all 512 threads): dim du, batch pair q ----
        {
            ull Ai = lds_u64(Pb + (unsigned)(((q * 2 + 0) * 256 + du) * 8));
            add2(Ai,  lds_u64(Pb + (unsigned)(((q * 2 + 1) * 256 + du) * 8)));
            ull Af = lds_u64(Pb + (unsigned)(((q * 2 + 0) * 256 + du + 128) * 8));
            add2(Af,  lds_u64(Pb + (unsigned)(((q * 2 + 1) * 256 + du + 128) * 8)));
            ull Ag = lds_u64(Pb + (unsigned)((((4 + q) * 2 + 0) * 256 + du) * 8));
            add2(Ag,  lds_u64(Pb + (unsigned)((((4 + q) * 2 + 1) * 256 + du) * 8)));
            ull Ao = lds_u64(Pb + (unsigned)((((4 + q) * 2 + 0) * 256 + du + 128) * 8));
            add2(Ao,  lds_u64(Pb + (unsigned)((((4 + q) * 2 + 1) * 256 + du + 128) * 8)));

            float i0 = sigm(lo2(Ai)), i1 = sigm(hi2(Ai));
            float f0 = sigm(lo2(Af)), f1 = sigm(hi2(Af));
            float g0 = tanh_(lo2(Ag)), g1 = tanh_(hi2(Ag));
            float o0 = sigm(lo2(Ao)), o1 = sigm(hi2(Ao));
            float c0 = fmaf(f0, cc0, i0 * g0);
            float c1 = fmaf(f1, cc1, i1 * g1);
            cc0 = c0; cc1 = c1;
            float h0 = o0 * tanh_(c0);
            float h1 = o1 * tanh_(c1);

            // padded k-major h + transposed copy
            sts_u64(hb + (unsigned)(du * 32 + (du >> 5) * 16 + q * 8), pack2(h0, h1));
            sHT[(2 * q) * 132 + du]     = h0;
            sHT[(2 * q + 1) * 132 + du] = h1;
        }
        __syncthreads();   // B3: h ready for next step
    }

    // ---- final readout: y_127 ----
    if (yth) {
        const float4* h4 = (const float4*)(sHT + yb * 132);
        const float4* w4 = (const float4*)(sWo + yn * 132);
        float ac0 = bo, ac1 = 0.0f, ac2 = 0.0f, ac3 = 0.0f;
        #pragma unroll 8
        for (int qq = 0; qq < 32; qq++) {
            float4 hq = h4[qq];
            float4 wq = w4[qq];
            ac0 = fmaf(hq.x, wq.x, ac0);
            ac1 = fmaf(hq.y, wq.y, ac1);
            ac2 = fmaf(hq.z, wq.z, ac2);
            ac3 = fmaf(hq.w, wq.w, ac3);
        }
        out[rowx + (T_SEQ - 1) * NB_] = (ac0 + ac1) + (ac2 + ac3);
    }
}

extern "C" void kernel_launch(void* const* d_in, const int* in_sizes, int n_in,
                              void* d_out, int out_size)
{
    const float* x     = (const float*)d_in[0];
    const float* W_ih  = (const float*)d_in[1];
    const float* W_hh  = (const float*)d_in[2];
    const float* b_ih  = (const float*)d_in[3];
    const float* b_hh  = (const float*)d_in[4];
    const float* W_out = (const float*)d_in[5];
    const float* b_out = (const float*)d_in[6];
    float* out = (float*)d_out;

    cudaFuncSetAttribute(lstm_main, cudaFuncAttributeMaxDynamicSharedMemorySize, SMEM_BYTES);

    prep_kernel<<<256, 256>>>(W_hh, W_ih, b_ih, b_hh);
    lstm_main<<<NBLOCKS, NTHREADS, SMEM_BYTES>>>(x, W_out, b_out, out);
}